// round 15
// baseline (speedup 1.0000x reference)
#include <cuda_runtime.h>
#include <cuda_fp16.h>
#include <cstdint>

#define Bn 64
#define Hn 256
#define Sn 4096

__device__ __half g_Wh[Hn * 512];
__device__ float g_scores[Bn * Sn];
__device__ float g_bias[Bn * Hn];

// ---- smem geometry (bytes) ----
// BK=32, BN=128. W: 3 stages 256 x 80B. X: 2 stages 32 x 272B.
#define W_STRIDE 80        // 32 fp16 (64B) + 16B pad
#define X_STRIDE 272       // 128 fp16 (256B) + 16B pad
#define W_STAGE 20480      // 256*80
#define X_STAGE 8704       // 32*272
#define OFF_X   61440      // 3*W_STAGE
#define SMEM_SZ (OFF_X + 2 * X_STAGE)

// ---------------- PTX helpers (baseline ISA only) ----------------
__device__ __forceinline__ uint32_t smem_u32(const void* p) {
    uint32_t a;
    asm("{ .reg .u64 t; cvta.to.shared.u64 t, %1; cvt.u32.u64 %0, t; }" : "=r"(a) : "l"(p));
    return a;
}
__device__ __forceinline__ void ldsm_x4(uint32_t* r, uint32_t addr) {
    asm volatile("ldmatrix.sync.aligned.m8n8.x4.shared.b16 {%0,%1,%2,%3}, [%4];"
                 : "=r"(r[0]), "=r"(r[1]), "=r"(r[2]), "=r"(r[3]) : "r"(addr));
}
__device__ __forceinline__ void ldsm_x4_t(uint32_t* r, uint32_t addr) {
    asm volatile("ldmatrix.sync.aligned.m8n8.x4.trans.shared.b16 {%0,%1,%2,%3}, [%4];"
                 : "=r"(r[0]), "=r"(r[1]), "=r"(r[2]), "=r"(r[3]) : "r"(addr));
}
__device__ __forceinline__ void mma_f16(float (&d)[4], const uint32_t (&a)[4],
                                        const uint32_t (&b)[2]) {
    asm volatile(
        "mma.sync.aligned.m16n8k16.row.col.f32.f16.f16.f32 "
        "{%0,%1,%2,%3}, {%4,%5,%6,%7}, {%8,%9}, {%0,%1,%2,%3};"
        : "+f"(d[0]), "+f"(d[1]), "+f"(d[2]), "+f"(d[3])
        : "r"(a[0]), "r"(a[1]), "r"(a[2]), "r"(a[3]), "r"(b[0]), "r"(b[1]));
}
#define CP_ASYNC16(s, g) \
    asm volatile("cp.async.cg.shared.global [%0], [%1], 16;" :: "r"(s), "l"(g))
#define CP_COMMIT() asm volatile("cp.async.commit_group;" ::: "memory")
#define CP_WAIT0()  asm volatile("cp.async.wait_group 0;" ::: "memory")
#define CP_WAIT1()  asm volatile("cp.async.wait_group 1;" ::: "memory")

__device__ __forceinline__ float tanh_acc(float x) {
    float z = x * 2.885390082f;           // 2*log2(e)*x
    float e; asm("ex2.approx.f32 %0, %1;" : "=f"(e) : "f"(z));
    float r; asm("rcp.approx.f32 %0, %1;" : "=f"(r) : "f"(e + 1.0f));
    return fmaf(-2.0f, r, 1.0f);          // 1 - 2/(e^{2x}+1)
}

// 8 floats -> 8 fp16 (one uint4)
__device__ __forceinline__ uint4 cvt8h(float4 a, float4 b) {
    __half2 p0 = __floats2half2_rn(a.x, a.y);
    __half2 p1 = __floats2half2_rn(a.z, a.w);
    __half2 p2 = __floats2half2_rn(b.x, b.y);
    __half2 p3 = __floats2half2_rn(b.z, b.w);
    return make_uint4(*(uint32_t*)&p0, *(uint32_t*)&p1,
                      *(uint32_t*)&p2, *(uint32_t*)&p3);
}

// ---------------------------------------------------------------------------
// Prep kernel, 2176 blocks x 256 threads (unchanged from R10).
// ---------------------------------------------------------------------------
__global__ void prep_kernel(const float* __restrict__ W,
                            const float* __restrict__ dh,
                            __half* __restrict__ wh,
                            float* __restrict__ bias) {
    int tid = threadIdx.x;
    if (blockIdx.x < 128) {
        int idx = blockIdx.x * 256 + tid;
        int h = idx >> 7, c4 = idx & 127;
        float4 w = *(const float4*)(W + (size_t)h * 768 + c4 * 4);
        __half2 h01 = __floats2half2_rn(w.x, w.y);
        __half2 h23 = __floats2half2_rn(w.z, w.w);
        uint2 hh = make_uint2(*(uint32_t*)&h01, *(uint32_t*)&h23);
        *(uint2*)(wh + (size_t)h * 512 + c4 * 4) = hh;
    } else {
        int g = blockIdx.x - 128;
        int b = g >> 5;
        int wid = tid >> 5, lane = tid & 31;
        int h = (g & 31) * 8 + wid;
        const float4* wr = (const float4*)(W + (size_t)h * 768 + 512);
        const float4* dr = (const float4*)(dh + (size_t)b * Hn);
        float4 w0 = __ldg(&wr[lane]);
        float4 w1 = __ldg(&wr[32 + lane]);
        float4 d0 = __ldg(&dr[lane]);
        float4 d1 = __ldg(&dr[32 + lane]);
        float s = w0.x * d0.x + w0.y * d0.y + w0.z * d0.z + w0.w * d0.w
                + w1.x * d1.x + w1.y * d1.y + w1.z * d1.z + w1.w * d1.w;
#pragma unroll
        for (int off = 16; off; off >>= 1)
            s += __shfl_xor_sync(0xffffffffu, s, off);
        if (lane == 0) bias[b * Hn + h] = s;
    }
}

// ---------------------------------------------------------------------------
// Main: grid (32 s-tiles, 64 b), 512 threads (16 warps: 4M x 4N).
// BM=256, BN=128, BK=32, 16 K-iters. Single-term fp16. 3-stage W pipeline.
// B fully resident per iter; A streamed (double-buffered) against MMAs;
// per-warp mt rotation to spread crossbar traffic.
// ---------------------------------------------------------------------------
__global__ __launch_bounds__(512, 1)
void attn_main(const float* __restrict__ SE, const float* __restrict__ DE,
               const __half* __restrict__ Wh,
               const float* __restrict__ v, const float* __restrict__ bias,
               float* __restrict__ scores) {
    extern __shared__ __align__(128) char smem[];
    const uint32_t sb = smem_u32(smem);
    const int tid = threadIdx.x, wid = tid >> 5, lane = tid & 31;
    const int wm = wid & 3, wn = wid >> 2;
    const int b = blockIdx.y;
    const int s0 = blockIdx.x * 128;

    const float* seb = SE + (size_t)b * Hn * Sn;
    const float* deb = DE + (size_t)b * Hn * Sn;

    const int kr = tid >> 4;          // 0..31
    const int c8 = (tid & 15) * 8;    // 0..120
    const int wrow = tid >> 1;
    const int wcol = (tid & 1) * 32;  // bytes

    float acc[4][4][4];
#pragma unroll
    for (int mt = 0; mt < 4; mt++)
#pragma unroll
        for (int nt = 0; nt < 4; nt++)
#pragma unroll
            for (int r = 0; r < 4; r++) acc[mt][nt][r] = 0.f;

    // ---- prologue: W stages 0,1 via cp.async, X stage0 via regs ----
    {
        const char* gw = (const char*)(Wh + (size_t)wrow * 512) + wcol;
        uint32_t sw = sb + wrow * W_STRIDE + wcol;
        CP_ASYNC16(sw, gw);
        CP_ASYNC16(sw + 16, gw + 16);
        CP_COMMIT();
        CP_ASYNC16(sw + W_STAGE, gw + 64);
        CP_ASYNC16(sw + W_STAGE + 16, gw + 64 + 16);
        CP_COMMIT();

        const float* base = seb + (size_t)kr * Sn + s0 + c8;
        float4 xa = *(const float4*)base;
        float4 xb = *(const float4*)(base + 4);
        uint32_t xoff = (uint32_t)(OFF_X + kr * X_STRIDE + (tid & 15) * 16);
        *(uint4*)(smem + xoff) = cvt8h(xa, xb);
    }

    const uint32_t arow = (uint32_t)((lane & 15) * W_STRIDE + (lane >> 4) * 16);
    const uint32_t xrow = (uint32_t)((lane & 15) * X_STRIDE + (lane >> 4) * 16);

    float4 xa, xb;
    for (int kc = 0; kc < 16; kc++) {
        const int bw = kc % 3;        // W stage
        const int bx = kc & 1;        // X stage
        if (kc == 15) { CP_WAIT0(); } else { CP_WAIT1(); }
        __syncthreads();

        if (kc < 14) {
            uint32_t s = sb + ((kc + 2) % 3) * W_STAGE + wrow * W_STRIDE + wcol;
            const char* gw = (const char*)(Wh + (size_t)wrow * 512 + (kc + 2) * 32) + wcol;
            CP_ASYNC16(s, gw);
            CP_ASYNC16(s + 16, gw + 16);
            CP_COMMIT();
        }
        if (kc < 15) {
            int kn = kc + 1;
            const float* base = ((kn < 8) ? seb : deb)
                              + (size_t)((kn & 7) * 32 + kr) * Sn + s0 + c8;
            xa = *(const float4*)base;
            xb = *(const float4*)(base + 4);
        }

        // ---- MMA: all B resident, A streamed with double buffer ----
        const uint32_t wbase = sb + bw * W_STAGE;
        const uint32_t xbase = sb + OFF_X + bx * X_STAGE;

        uint32_t bH[2][4][2];
#pragma unroll
        for (int ks = 0; ks < 2; ks++)
#pragma unroll
            for (int np = 0; np < 2; np++) {
                uint32_t bd = xbase
                    + (uint32_t)(ks * 16 * X_STRIDE + (wn * 32 + np * 16) * 2) + xrow;
                uint32_t t[4];
                ldsm_x4_t(t, bd);
                bH[ks][2 * np][0] = t[0];     bH[ks][2 * np][1] = t[1];
                bH[ks][2 * np + 1][0] = t[2]; bH[ks][2 * np + 1][1] = t[3];
            }

        // A stream: 8 rows (ks major, mt rotated by wm), db in aH[2]
        uint32_t aH[2][4];
        {
            const int mt0 = wm & 3;   // rotation start
            uint32_t ad0 = wbase + (uint32_t)((wm * 64 + mt0 * 16) * W_STRIDE) + arow;
            ldsm_x4(aH[0], ad0);
        }
#pragma unroll
        for (int i = 0; i < 8; i++) {
            const int ks = i >> 2;
            const int mt = ((i & 3) + wm) & 3;
            if (i < 7) {
                const int ksn = (i + 1) >> 2;
                const int mtn = (((i + 1) & 3) + wm) & 3;
                uint32_t adn = wbase
                    + (uint32_t)((wm * 64 + mtn * 16) * W_STRIDE + ksn * 32) + arow;
                ldsm_x4(aH[(i + 1) & 1], adn);
            }
#pragma unroll
            for (int nt = 0; nt < 4; nt++)
                mma_f16(acc[mt][nt], aH[i & 1], bH[ks][nt]);
        }

        if (kc < 15) {
            uint32_t xoff = (uint32_t)(OFF_X + (bx ^ 1) * X_STAGE
                                       + kr * X_STRIDE + (tid & 15) * 16);
            *(uint4*)(smem + xoff) = cvt8h(xa, xb);
        }
    }

    // ---- epilogue: p = v[h]*tanh(acc+bias[h]); reduce over h ----
    float colsum[4][2];
#pragma unroll
    for (int nt = 0; nt < 4; nt++) { colsum[nt][0] = 0.f; colsum[nt][1] = 0.f; }

#pragma unroll
    for (int mt = 0; mt < 4; mt++) {
        int h0 = wm * 64 + mt * 16 + (lane >> 2);
        float bi0 = bias[b * Hn + h0],     v0 = v[h0];
        float bi1 = bias[b * Hn + h0 + 8], v1 = v[h0 + 8];
#pragma unroll
        for (int nt = 0; nt < 4; nt++) {
            colsum[nt][0] += v0 * tanh_acc(acc[mt][nt][0] + bi0)
                           + v1 * tanh_acc(acc[mt][nt][2] + bi1);
            colsum[nt][1] += v0 * tanh_acc(acc[mt][nt][1] + bi0)
                           + v1 * tanh_acc(acc[mt][nt][3] + bi1);
        }
    }
#pragma unroll
    for (int off = 4; off < 32; off <<= 1)
#pragma unroll
        for (int nt = 0; nt < 4; nt++) {
            colsum[nt][0] += __shfl_xor_sync(0xffffffffu, colsum[nt][0], off);
            colsum[nt][1] += __shfl_xor_sync(0xffffffffu, colsum[nt][1], off);
        }

    __syncthreads();  // stage data no longer needed
    float* spart = (float*)smem;  // [4][128]
    if (lane < 4) {
#pragma unroll
        for (int nt = 0; nt < 4; nt++) {
            spart[wm * 128 + wn * 32 + nt * 8 + lane * 2 + 0] = colsum[nt][0];
            spart[wm * 128 + wn * 32 + nt * 8 + lane * 2 + 1] = colsum[nt][1];
        }
    }
    __syncthreads();
    if (tid < 128) {
        float sc = spart[tid] + spart[128 + tid] + spart[256 + tid] + spart[384 + tid];
        scores[(size_t)b * Sn + s0 + tid] = sc;
    }
}

// ---------------------------------------------------------------------------
__global__ void softmax_kernel(const float* __restrict__ scores,
                               float* __restrict__ out) {
    const int b = blockIdx.x, tid = threadIdx.x;
    const float* row = scores + (size_t)b * Sn;
    float vals[16];
    float mx = -1e30f;
#pragma unroll
    for (int i = 0; i < 16; i++) {
        vals[i] = row[tid + i * 256];
        mx = fmaxf(mx, vals[i]);
    }
#pragma unroll
    for (int off = 16; off; off >>= 1)
        mx = fmaxf(mx, __shfl_xor_sync(0xffffffffu, mx, off));
    __shared__ float sred[8];
    if ((tid & 31) == 0) sred[tid >> 5] = mx;
    __syncthreads();
    float bm = sred[0];
#pragma unroll
    for (int w = 1; w < 8; w++) bm = fmaxf(bm, sred[w]);
    __syncthreads();
    float sum = 0.f;
#pragma unroll
    for (int i = 0; i < 16; i++) { vals[i] = __expf(vals[i] - bm); sum += vals[i]; }
#pragma unroll
    for (int off = 16; off; off >>= 1)
        sum += __shfl_xor_sync(0xffffffffu, sum, off);
    if ((tid & 31) == 0) sred[tid >> 5] = sum;
    __syncthreads();
    float tot = 0.f;
#pragma unroll
    for (int w = 0; w < 8; w++) tot += sred[w];
    float inv = 1.0f / tot;
#pragma unroll
    for (int i = 0; i < 16; i++)
        out[(size_t)b * Sn + tid + i * 256] = vals[i] * inv;
}

// ---------------------------------------------------------------------------
extern "C" void kernel_launch(void* const* d_in, const int* in_sizes, int n_in,
                              void* d_out, int out_size) {
    const float* SE = (const float*)d_in[0];
    const float* DE = (const float*)d_in[1];
    const float* dh = (const float*)d_in[2];
    const float* v  = (const float*)d_in[3];
    const float* W  = (const float*)d_in[4];
    float* out = (float*)d_out;

    __half *wh; float *bias, *scores;
    cudaGetSymbolAddress((void**)&wh, g_Wh);
    cudaGetSymbolAddress((void**)&bias, g_bias);
    cudaGetSymbolAddress((void**)&scores, g_scores);

    cudaFuncSetAttribute(attn_main, cudaFuncAttributeMaxDynamicSharedMemorySize, SMEM_SZ);

    prep_kernel<<<2176, 256>>>(W, dh, wh, bias);
    attn_main<<<dim3(32, Bn), 512, SMEM_SZ>>>(SE, DE, wh, v, bias, scores);
    softmax_kernel<<<Bn, 256>>>(scores, out);
}

// round 16
// speedup vs baseline: 5.1827x; 5.1827x over previous
#include <cuda_runtime.h>
#include <cuda_fp16.h>
#include <cstdint>

#define Bn 64
#define Hn 256
#define Sn 4096

__device__ __half g_Wh[Hn * 512];
__device__ float g_scores[Bn * Sn];
__device__ float g_bias[Bn * Hn];

// ---- smem geometry (bytes) ----
// BK=32, BN=128. W: 3 stages 256 x 80B. X: 2 stages 32 x 272B.
#define W_STRIDE 80        // 32 fp16 (64B) + 16B pad
#define X_STRIDE 272       // 128 fp16 (256B) + 16B pad
#define W_STAGE 20480      // 256*80
#define X_STAGE 8704       // 32*272
#define OFF_X   61440      // 3*W_STAGE
#define SMEM_SZ (OFF_X + 2 * X_STAGE)

// ---------------- PTX helpers (baseline ISA only) ----------------
__device__ __forceinline__ uint32_t smem_u32(const void* p) {
    uint32_t a;
    asm("{ .reg .u64 t; cvta.to.shared.u64 t, %1; cvt.u32.u64 %0, t; }" : "=r"(a) : "l"(p));
    return a;
}
__device__ __forceinline__ void ldsm_x4(uint32_t* r, uint32_t addr) {
    asm volatile("ldmatrix.sync.aligned.m8n8.x4.shared.b16 {%0,%1,%2,%3}, [%4];"
                 : "=r"(r[0]), "=r"(r[1]), "=r"(r[2]), "=r"(r[3]) : "r"(addr));
}
__device__ __forceinline__ void ldsm_x4_t(uint32_t* r, uint32_t addr) {
    asm volatile("ldmatrix.sync.aligned.m8n8.x4.trans.shared.b16 {%0,%1,%2,%3}, [%4];"
                 : "=r"(r[0]), "=r"(r[1]), "=r"(r[2]), "=r"(r[3]) : "r"(addr));
}
__device__ __forceinline__ void mma_f16(float (&d)[4], const uint32_t (&a)[4],
                                        const uint32_t (&b)[2]) {
    asm volatile(
        "mma.sync.aligned.m16n8k16.row.col.f32.f16.f16.f32 "
        "{%0,%1,%2,%3}, {%4,%5,%6,%7}, {%8,%9}, {%0,%1,%2,%3};"
        : "+f"(d[0]), "+f"(d[1]), "+f"(d[2]), "+f"(d[3])
        : "r"(a[0]), "r"(a[1]), "r"(a[2]), "r"(a[3]), "r"(b[0]), "r"(b[1]));
}
#define CP_ASYNC16(s, g) \
    asm volatile("cp.async.cg.shared.global [%0], [%1], 16;" :: "r"(s), "l"(g))
#define CP_COMMIT() asm volatile("cp.async.commit_group;" ::: "memory")
#define CP_WAIT0()  asm volatile("cp.async.wait_group 0;" ::: "memory")
#define CP_WAIT1()  asm volatile("cp.async.wait_group 1;" ::: "memory")

__device__ __forceinline__ float tanh_acc(float x) {
    float z = x * 2.885390082f;           // 2*log2(e)*x
    float e; asm("ex2.approx.f32 %0, %1;" : "=f"(e) : "f"(z));
    float r; asm("rcp.approx.f32 %0, %1;" : "=f"(r) : "f"(e + 1.0f));
    return fmaf(-2.0f, r, 1.0f);          // 1 - 2/(e^{2x}+1)
}

// 8 floats -> 8 fp16 (one uint4)
__device__ __forceinline__ uint4 cvt8h(float4 a, float4 b) {
    __half2 p0 = __floats2half2_rn(a.x, a.y);
    __half2 p1 = __floats2half2_rn(a.z, a.w);
    __half2 p2 = __floats2half2_rn(b.x, b.y);
    __half2 p3 = __floats2half2_rn(b.z, b.w);
    return make_uint4(*(uint32_t*)&p0, *(uint32_t*)&p1,
                      *(uint32_t*)&p2, *(uint32_t*)&p3);
}

// ---------------------------------------------------------------------------
// Prep kernel, 2176 blocks x 256 threads.
//  blocks 0..127: convert W[:, :512] -> fp16 (coalesced float4 per thread)
//  blocks 128..2175: bias. One warp per (b, h): coalesced row dot product.
// ---------------------------------------------------------------------------
__global__ void prep_kernel(const float* __restrict__ W,
                            const float* __restrict__ dh,
                            __half* __restrict__ wh,
                            float* __restrict__ bias) {
    int tid = threadIdx.x;
    if (blockIdx.x < 128) {
        int idx = blockIdx.x * 256 + tid;
        int h = idx >> 7, c4 = idx & 127;
        float4 w = *(const float4*)(W + (size_t)h * 768 + c4 * 4);
        __half2 h01 = __floats2half2_rn(w.x, w.y);
        __half2 h23 = __floats2half2_rn(w.z, w.w);
        uint2 hh = make_uint2(*(uint32_t*)&h01, *(uint32_t*)&h23);
        *(uint2*)(wh + (size_t)h * 512 + c4 * 4) = hh;
    } else {
        int g = blockIdx.x - 128;
        int b = g >> 5;
        int wid = tid >> 5, lane = tid & 31;
        int h = (g & 31) * 8 + wid;
        const float4* wr = (const float4*)(W + (size_t)h * 768 + 512);
        const float4* dr = (const float4*)(dh + (size_t)b * Hn);
        float4 w0 = __ldg(&wr[lane]);
        float4 w1 = __ldg(&wr[32 + lane]);
        float4 d0 = __ldg(&dr[lane]);
        float4 d1 = __ldg(&dr[32 + lane]);
        float s = w0.x * d0.x + w0.y * d0.y + w0.z * d0.z + w0.w * d0.w
                + w1.x * d1.x + w1.y * d1.y + w1.z * d1.z + w1.w * d1.w;
#pragma unroll
        for (int off = 16; off; off >>= 1)
            s += __shfl_xor_sync(0xffffffffu, s, off);
        if (lane == 0) bias[b * Hn + h] = s;
    }
}

// ---------------------------------------------------------------------------
// Main: grid (32 s-tiles, 64 b), 512 threads (16 warps: 4M x 4N).
// BM=256, BN=128, BK=32, 16 K-iters. Single-term fp16. 3-stage W pipeline.
// A-fragment double buffering (compile-time indices only).
// ---------------------------------------------------------------------------
__global__ __launch_bounds__(512, 1)
void attn_main(const float* __restrict__ SE, const float* __restrict__ DE,
               const __half* __restrict__ Wh,
               const float* __restrict__ v, const float* __restrict__ bias,
               float* __restrict__ scores) {
    extern __shared__ __align__(128) char smem[];
    const uint32_t sb = smem_u32(smem);
    const int tid = threadIdx.x, wid = tid >> 5, lane = tid & 31;
    const int wm = wid & 3, wn = wid >> 2;
    const int b = blockIdx.y;
    const int s0 = blockIdx.x * 128;

    const float* seb = SE + (size_t)b * Hn * Sn;
    const float* deb = DE + (size_t)b * Hn * Sn;

    const int kr = tid >> 4;          // 0..31
    const int c8 = (tid & 15) * 8;    // 0..120
    const int wrow = tid >> 1;
    const int wcol = (tid & 1) * 32;  // bytes

    float acc[4][4][4];
#pragma unroll
    for (int mt = 0; mt < 4; mt++)
#pragma unroll
        for (int nt = 0; nt < 4; nt++)
#pragma unroll
            for (int r = 0; r < 4; r++) acc[mt][nt][r] = 0.f;

    // ---- prologue: W stages 0,1 via cp.async, X stage0 via regs ----
    {
        const char* gw = (const char*)(Wh + (size_t)wrow * 512) + wcol;
        uint32_t sw = sb + wrow * W_STRIDE + wcol;
        CP_ASYNC16(sw, gw);
        CP_ASYNC16(sw + 16, gw + 16);
        CP_COMMIT();
        CP_ASYNC16(sw + W_STAGE, gw + 64);
        CP_ASYNC16(sw + W_STAGE + 16, gw + 64 + 16);
        CP_COMMIT();

        const float* base = seb + (size_t)kr * Sn + s0 + c8;
        float4 xa = *(const float4*)base;
        float4 xb = *(const float4*)(base + 4);
        uint32_t xoff = (uint32_t)(OFF_X + kr * X_STRIDE + (tid & 15) * 16);
        *(uint4*)(smem + xoff) = cvt8h(xa, xb);
    }

    const uint32_t arow = (uint32_t)((lane & 15) * W_STRIDE + (lane >> 4) * 16);
    const uint32_t xrow = (uint32_t)((lane & 15) * X_STRIDE + (lane >> 4) * 16);

    float4 xa, xb;
    for (int kc = 0; kc < 16; kc++) {
        const int bw = kc % 3;        // W stage
        const int bx = kc & 1;        // X stage
        if (kc == 15) { CP_WAIT0(); } else { CP_WAIT1(); }
        __syncthreads();

        if (kc < 14) {
            uint32_t s = sb + ((kc + 2) % 3) * W_STAGE + wrow * W_STRIDE + wcol;
            const char* gw = (const char*)(Wh + (size_t)wrow * 512 + (kc + 2) * 32) + wcol;
            CP_ASYNC16(s, gw);
            CP_ASYNC16(s + 16, gw + 16);
            CP_COMMIT();
        }
        if (kc < 15) {
            int kn = kc + 1;
            const float* base = ((kn < 8) ? seb : deb)
                              + (size_t)((kn & 7) * 32 + kr) * Sn + s0 + c8;
            xa = *(const float4*)base;
            xb = *(const float4*)(base + 4);
        }

        // ---- MMA on W stage bw, X stage bx, A double-buffered over mt ----
        const uint32_t wbase = sb + bw * W_STAGE;
        const uint32_t xbase = sb + OFF_X + bx * X_STAGE;
#pragma unroll
        for (int ks = 0; ks < 2; ks++) {
            uint32_t bH[4][2];
#pragma unroll
            for (int np = 0; np < 2; np++) {
                uint32_t bd = xbase
                    + (uint32_t)(ks * 16 * X_STRIDE + (wn * 32 + np * 16) * 2) + xrow;
                uint32_t t[4];
                ldsm_x4_t(t, bd);
                bH[2 * np][0] = t[0];     bH[2 * np][1] = t[1];
                bH[2 * np + 1][0] = t[2]; bH[2 * np + 1][1] = t[3];
            }
            const uint32_t ad0 = wbase + (uint32_t)(wm * 64 * W_STRIDE + ks * 32) + arow;
            uint32_t aH[2][4];
            ldsm_x4(aH[0], ad0);
#pragma unroll
            for (int mt = 0; mt < 4; mt++) {
                if (mt < 3)
                    ldsm_x4(aH[(mt + 1) & 1], ad0 + (uint32_t)((mt + 1) * 16 * W_STRIDE));
#pragma unroll
                for (int nt = 0; nt < 4; nt++)
                    mma_f16(acc[mt][nt], aH[mt & 1], bH[nt]);
            }
        }

        if (kc < 15) {
            uint32_t xoff = (uint32_t)(OFF_X + (bx ^ 1) * X_STAGE
                                       + kr * X_STRIDE + (tid & 15) * 16);
            *(uint4*)(smem + xoff) = cvt8h(xa, xb);
        }
    }

    // ---- epilogue: p = v[h]*tanh(acc+bias[h]); reduce over h ----
    float colsum[4][2];
#pragma unroll
    for (int nt = 0; nt < 4; nt++) { colsum[nt][0] = 0.f; colsum[nt][1] = 0.f; }

#pragma unroll
    for (int mt = 0; mt < 4; mt++) {
        int h0 = wm * 64 + mt * 16 + (lane >> 2);
        float bi0 = bias[b * Hn + h0],     v0 = v[h0];
        float bi1 = bias[b * Hn + h0 + 8], v1 = v[h0 + 8];
#pragma unroll
        for (int nt = 0; nt < 4; nt++) {
            colsum[nt][0] += v0 * tanh_acc(acc[mt][nt][0] + bi0)
                           + v1 * tanh_acc(acc[mt][nt][2] + bi1);
            colsum[nt][1] += v0 * tanh_acc(acc[mt][nt][1] + bi0)
                           + v1 * tanh_acc(acc[mt][nt][3] + bi1);
        }
    }
#pragma unroll
    for (int off = 4; off < 32; off <<= 1)
#pragma unroll
        for (int nt = 0; nt < 4; nt++) {
            colsum[nt][0] += __shfl_xor_sync(0xffffffffu, colsum[nt][0], off);
            colsum[nt][1] += __shfl_xor_sync(0xffffffffu, colsum[nt][1], off);
        }

    __syncthreads();  // stage data no longer needed
    float* spart = (float*)smem;  // [4][128]
    if (lane < 4) {
#pragma unroll
        for (int nt = 0; nt < 4; nt++) {
            spart[wm * 128 + wn * 32 + nt * 8 + lane * 2 + 0] = colsum[nt][0];
            spart[wm * 128 + wn * 32 + nt * 8 + lane * 2 + 1] = colsum[nt][1];
        }
    }
    __syncthreads();
    if (tid < 128) {
        float sc = spart[tid] + spart[128 + tid] + spart[256 + tid] + spart[384 + tid];
        scores[(size_t)b * Sn + s0 + tid] = sc;
    }
}

// ---------------------------------------------------------------------------
__global__ void softmax_kernel(const float* __restrict__ scores,
                               float* __restrict__ out) {
    const int b = blockIdx.x, tid = threadIdx.x;
    const float* row = scores + (size_t)b * Sn;
    float vals[16];
    float mx = -1e30f;
#pragma unroll
    for (int i = 0; i < 16; i++) {
        vals[i] = row[tid + i * 256];
        mx = fmaxf(mx, vals[i]);
    }
#pragma unroll
    for (int off = 16; off; off >>= 1)
        mx = fmaxf(mx, __shfl_xor_sync(0xffffffffu, mx, off));
    __shared__ float sred[8];
    if ((tid & 31) == 0) sred[tid >> 5] = mx;
    __syncthreads();
    float bm = sred[0];
#pragma unroll
    for (int w = 1; w < 8; w++) bm = fmaxf(bm, sred[w]);
    __syncthreads();
    float sum = 0.f;
#pragma unroll
    for (int i = 0; i < 16; i++) { vals[i] = __expf(vals[i] - bm); sum += vals[i]; }
#pragma unroll
    for (int off = 16; off; off >>= 1)
        sum += __shfl_xor_sync(0xffffffffu, sum, off);
    if ((tid & 31) == 0) sred[tid >> 5] = sum;
    __syncthreads();
    float tot = 0.f;
#pragma unroll
    for (int w = 0; w < 8; w++) tot += sred[w];
    float inv = 1.0f / tot;
#pragma unroll
    for (int i = 0; i < 16; i++)
        out[(size_t)b * Sn + tid + i * 256] = vals[i] * inv;
}

// ---------------------------------------------------------------------------
extern "C" void kernel_launch(void* const* d_in, const int* in_sizes, int n_in,
                              void* d_out, int out_size) {
    const float* SE = (const float*)d_in[0];
    const float* DE = (const float*)d_in[1];
    const float* dh = (const float*)d_in[2];
    const float* v  = (const float*)d_in[3];
    const float* W  = (const float*)d_in[4];
    float* out = (float*)d_out;

    __half *wh; float *bias, *scores;
    cudaGetSymbolAddress((void**)&wh, g_Wh);
    cudaGetSymbolAddress((void**)&bias, g_bias);
    cudaGetSymbolAddress((void**)&scores, g_scores);

    cudaFuncSetAttribute(attn_main, cudaFuncAttributeMaxDynamicSharedMemorySize, SMEM_SZ);

    prep_kernel<<<2176, 256>>>(W, dh, wh, bias);
    attn_main<<<dim3(32, Bn), 512, SMEM_SZ>>>(SE, DE, wh, v, bias, scores);
    softmax_kernel<<<Bn, 256>>>(scores, out);
}

// round 17
// speedup vs baseline: 5.1840x; 1.0002x over previous
#include <cuda_runtime.h>
#include <cuda_fp16.h>
#include <cstdint>

#define Bn 64
#define Hn 256
#define Sn 4096

__device__ __half g_Wh[Hn * 512];
__device__ float g_scores[Bn * Sn];
__device__ float g_bias[Bn * Hn];

// ---- smem geometry (bytes) ----
// BK=32, BN=128. W: 3 stages 256 x 80B. X: 2 stages 32 x 272B.
#define W_STRIDE 80        // 32 fp16 (64B) + 16B pad
#define X_STRIDE 272       // 128 fp16 (256B) + 16B pad
#define W_STAGE 20480      // 256*80
#define X_STAGE 8704       // 32*272
#define OFF_X   61440      // 3*W_STAGE
#define SMEM_SZ (OFF_X + 2 * X_STAGE)

// ---------------- PTX helpers (baseline ISA only) ----------------
__device__ __forceinline__ uint32_t smem_u32(const void* p) {
    uint32_t a;
    asm("{ .reg .u64 t; cvta.to.shared.u64 t, %1; cvt.u32.u64 %0, t; }" : "=r"(a) : "l"(p));
    return a;
}
__device__ __forceinline__ void ldsm_x4(uint32_t* r, uint32_t addr) {
    asm volatile("ldmatrix.sync.aligned.m8n8.x4.shared.b16 {%0,%1,%2,%3}, [%4];"
                 : "=r"(r[0]), "=r"(r[1]), "=r"(r[2]), "=r"(r[3]) : "r"(addr));
}
__device__ __forceinline__ void ldsm_x4_t(uint32_t* r, uint32_t addr) {
    asm volatile("ldmatrix.sync.aligned.m8n8.x4.trans.shared.b16 {%0,%1,%2,%3}, [%4];"
                 : "=r"(r[0]), "=r"(r[1]), "=r"(r[2]), "=r"(r[3]) : "r"(addr));
}
__device__ __forceinline__ void mma_f16(float (&d)[4], const uint32_t (&a)[4],
                                        const uint32_t (&b)[2]) {
    asm volatile(
        "mma.sync.aligned.m16n8k16.row.col.f32.f16.f16.f32 "
        "{%0,%1,%2,%3}, {%4,%5,%6,%7}, {%8,%9}, {%0,%1,%2,%3};"
        : "+f"(d[0]), "+f"(d[1]), "+f"(d[2]), "+f"(d[3])
        : "r"(a[0]), "r"(a[1]), "r"(a[2]), "r"(a[3]), "r"(b[0]), "r"(b[1]));
}
#define CP_ASYNC16(s, g) \
    asm volatile("cp.async.cg.shared.global [%0], [%1], 16;" :: "r"(s), "l"(g))
#define CP_COMMIT() asm volatile("cp.async.commit_group;" ::: "memory")
#define CP_WAIT0()  asm volatile("cp.async.wait_group 0;" ::: "memory")
#define CP_WAIT1()  asm volatile("cp.async.wait_group 1;" ::: "memory")

__device__ __forceinline__ float tanh_acc(float x) {
    float z = x * 2.885390082f;           // 2*log2(e)*x
    float e; asm("ex2.approx.f32 %0, %1;" : "=f"(e) : "f"(z));
    float r; asm("rcp.approx.f32 %0, %1;" : "=f"(r) : "f"(e + 1.0f));
    return fmaf(-2.0f, r, 1.0f);          // 1 - 2/(e^{2x}+1)
}

// 8 floats -> 8 fp16 (one uint4)
__device__ __forceinline__ uint4 cvt8h(float4 a, float4 b) {
    __half2 p0 = __floats2half2_rn(a.x, a.y);
    __half2 p1 = __floats2half2_rn(a.z, a.w);
    __half2 p2 = __floats2half2_rn(b.x, b.y);
    __half2 p3 = __floats2half2_rn(b.z, b.w);
    return make_uint4(*(uint32_t*)&p0, *(uint32_t*)&p1,
                      *(uint32_t*)&p2, *(uint32_t*)&p3);
}

// ---------------------------------------------------------------------------
// Prep kernel, 2176 blocks x 256 threads.
//  blocks 0..127: convert W[:, :512] -> fp16 (coalesced float4 per thread)
//  blocks 128..2175: bias. One warp per (b, h): coalesced row dot product.
// ---------------------------------------------------------------------------
__global__ void prep_kernel(const float* __restrict__ W,
                            const float* __restrict__ dh,
                            __half* __restrict__ wh,
                            float* __restrict__ bias) {
    int tid = threadIdx.x;
    if (blockIdx.x < 128) {
        int idx = blockIdx.x * 256 + tid;
        int h = idx >> 7, c4 = idx & 127;
        float4 w = *(const float4*)(W + (size_t)h * 768 + c4 * 4);
        __half2 h01 = __floats2half2_rn(w.x, w.y);
        __half2 h23 = __floats2half2_rn(w.z, w.w);
        uint2 hh = make_uint2(*(uint32_t*)&h01, *(uint32_t*)&h23);
        *(uint2*)(wh + (size_t)h * 512 + c4 * 4) = hh;
    } else {
        int g = blockIdx.x - 128;
        int b = g >> 5;
        int wid = tid >> 5, lane = tid & 31;
        int h = (g & 31) * 8 + wid;
        const float4* wr = (const float4*)(W + (size_t)h * 768 + 512);
        const float4* dr = (const float4*)(dh + (size_t)b * Hn);
        float4 w0 = __ldg(&wr[lane]);
        float4 w1 = __ldg(&wr[32 + lane]);
        float4 d0 = __ldg(&dr[lane]);
        float4 d1 = __ldg(&dr[32 + lane]);
        float s = w0.x * d0.x + w0.y * d0.y + w0.z * d0.z + w0.w * d0.w
                + w1.x * d1.x + w1.y * d1.y + w1.z * d1.z + w1.w * d1.w;
#pragma unroll
        for (int off = 16; off; off >>= 1)
            s += __shfl_xor_sync(0xffffffffu, s, off);
        if (lane == 0) bias[b * Hn + h] = s;
    }
}

// ---------------------------------------------------------------------------
// Main: grid (32 s-tiles, 64 b), 512 threads (16 warps: 4M x 4N).
// BM=256, BN=128, BK=32, 16 K-iters. Single-term fp16. 3-stage W pipeline.
// A-fragment double buffering. X LDGs hoisted above the barrier so the
// post-barrier LSU burst is LDSM-only.
// ---------------------------------------------------------------------------
__global__ __launch_bounds__(512, 1)
void attn_main(const float* __restrict__ SE, const float* __restrict__ DE,
               const __half* __restrict__ Wh,
               const float* __restrict__ v, const float* __restrict__ bias,
               float* __restrict__ scores) {
    extern __shared__ __align__(128) char smem[];
    const uint32_t sb = smem_u32(smem);
    const int tid = threadIdx.x, wid = tid >> 5, lane = tid & 31;
    const int wm = wid & 3, wn = wid >> 2;
    const int b = blockIdx.y;
    const int s0 = blockIdx.x * 128;

    const float* seb = SE + (size_t)b * Hn * Sn;
    const float* deb = DE + (size_t)b * Hn * Sn;

    const int kr = tid >> 4;          // 0..31
    const int c8 = (tid & 15) * 8;    // 0..120
    const int wrow = tid >> 1;
    const int wcol = (tid & 1) * 32;  // bytes

    float acc[4][4][4];
#pragma unroll
    for (int mt = 0; mt < 4; mt++)
#pragma unroll
        for (int nt = 0; nt < 4; nt++)
#pragma unroll
            for (int r = 0; r < 4; r++) acc[mt][nt][r] = 0.f;

    // ---- prologue: W stages 0,1 via cp.async, X stage0 via regs ----
    {
        const char* gw = (const char*)(Wh + (size_t)wrow * 512) + wcol;
        uint32_t sw = sb + wrow * W_STRIDE + wcol;
        CP_ASYNC16(sw, gw);
        CP_ASYNC16(sw + 16, gw + 16);
        CP_COMMIT();
        CP_ASYNC16(sw + W_STAGE, gw + 64);
        CP_ASYNC16(sw + W_STAGE + 16, gw + 64 + 16);
        CP_COMMIT();

        const float* base = seb + (size_t)kr * Sn + s0 + c8;
        float4 xa = *(const float4*)base;
        float4 xb = *(const float4*)(base + 4);
        uint32_t xoff = (uint32_t)(OFF_X + kr * X_STRIDE + (tid & 15) * 16);
        *(uint4*)(smem + xoff) = cvt8h(xa, xb);
    }

    const uint32_t arow = (uint32_t)((lane & 15) * W_STRIDE + (lane >> 4) * 16);
    const uint32_t xrow = (uint32_t)((lane & 15) * X_STRIDE + (lane >> 4) * 16);

    float4 xa, xb;
    for (int kc = 0; kc < 16; kc++) {
        const int bw = kc % 3;        // W stage
        const int bx = kc & 1;        // X stage

        // X(kc+1) gmem loads issued BEFORE the barrier: overlap previous MMA
        // drain + barrier wait; post-barrier LSU burst becomes LDSM-only.
        if (kc < 15) {
            int kn = kc + 1;
            const float* base = ((kn < 8) ? seb : deb)
                              + (size_t)((kn & 7) * 32 + kr) * Sn + s0 + c8;
            xa = *(const float4*)base;
            xb = *(const float4*)(base + 4);
        }

        if (kc == 15) { CP_WAIT0(); } else { CP_WAIT1(); }
        __syncthreads();

        if (kc < 14) {
            uint32_t s = sb + ((kc + 2) % 3) * W_STAGE + wrow * W_STRIDE + wcol;
            const char* gw = (const char*)(Wh + (size_t)wrow * 512 + (kc + 2) * 32) + wcol;
            CP_ASYNC16(s, gw);
            CP_ASYNC16(s + 16, gw + 16);
            CP_COMMIT();
        }

        // ---- MMA on W stage bw, X stage bx, A double-buffered over mt ----
        const uint32_t wbase = sb + bw * W_STAGE;
        const uint32_t xbase = sb + OFF_X + bx * X_STAGE;
#pragma unroll
        for (int ks = 0; ks < 2; ks++) {
            uint32_t bH[4][2];
#pragma unroll
            for (int np = 0; np < 2; np++) {
                uint32_t bd = xbase
                    + (uint32_t)(ks * 16 * X_STRIDE + (wn * 32 + np * 16) * 2) + xrow;
                uint32_t t[4];
                ldsm_x4_t(t, bd);
                bH[2 * np][0] = t[0];     bH[2 * np][1] = t[1];
                bH[2 * np + 1][0] = t[2]; bH[2 * np + 1][1] = t[3];
            }
            const uint32_t ad0 = wbase + (uint32_t)(wm * 64 * W_STRIDE + ks * 32) + arow;
            uint32_t aH[2][4];
            ldsm_x4(aH[0], ad0);
#pragma unroll
            for (int mt = 0; mt < 4; mt++) {
                if (mt < 3)
                    ldsm_x4(aH[(mt + 1) & 1], ad0 + (uint32_t)((mt + 1) * 16 * W_STRIDE));
#pragma unroll
                for (int nt = 0; nt < 4; nt++)
                    mma_f16(acc[mt][nt], aH[mt & 1], bH[nt]);
            }
        }

        if (kc < 15) {
            uint32_t xoff = (uint32_t)(OFF_X + (bx ^ 1) * X_STAGE
                                       + kr * X_STRIDE + (tid & 15) * 16);
            *(uint4*)(smem + xoff) = cvt8h(xa, xb);
        }
    }

    // ---- epilogue: p = v[h]*tanh(acc+bias[h]); reduce over h ----
    float colsum[4][2];
#pragma unroll
    for (int nt = 0; nt < 4; nt++) { colsum[nt][0] = 0.f; colsum[nt][1] = 0.f; }

#pragma unroll
    for (int mt = 0; mt < 4; mt++) {
        int h0 = wm * 64 + mt * 16 + (lane >> 2);
        float bi0 = bias[b * Hn + h0],     v0 = v[h0];
        float bi1 = bias[b * Hn + h0 + 8], v1 = v[h0 + 8];
#pragma unroll
        for (int nt = 0; nt < 4; nt++) {
            colsum[nt][0] += v0 * tanh_acc(acc[mt][nt][0] + bi0)
                           + v1 * tanh_acc(acc[mt][nt][2] + bi1);
            colsum[nt][1] += v0 * tanh_acc(acc[mt][nt][1] + bi0)
                           + v1 * tanh_acc(acc[mt][nt][3] + bi1);
        }
    }
#pragma unroll
    for (int off = 4; off < 32; off <<= 1)
#pragma unroll
        for (int nt = 0; nt < 4; nt++) {
            colsum[nt][0] += __shfl_xor_sync(0xffffffffu, colsum[nt][0], off);
            colsum[nt][1] += __shfl_xor_sync(0xffffffffu, colsum[nt][1], off);
        }

    __syncthreads();  // stage data no longer needed
    float* spart = (float*)smem;  // [4][128]
    if (lane < 4) {
#pragma unroll
        for (int nt = 0; nt < 4; nt++) {
            spart[wm * 128 + wn * 32 + nt * 8 + lane * 2 + 0] = colsum[nt][0];
            spart[wm * 128 + wn * 32 + nt * 8 + lane * 2 + 1] = colsum[nt][1];
        }
    }
    __syncthreads();
    if (tid < 128) {
        float sc = spart[tid] + spart[128 + tid] + spart[256 + tid] + spart[384 + tid];
        scores[(size_t)b * Sn + s0 + tid] = sc;
    }
}

// ---------------------------------------------------------------------------
__global__ void softmax_kernel(const float* __restrict__ scores,
                               float* __restrict__ out) {
    const int b = blockIdx.x, tid = threadIdx.x;
    const float* row = scores + (size_t)b * Sn;
    float vals[16];
    float mx = -1e30f;
#pragma unroll
    for (int i = 0; i < 16; i++) {
        vals[i] = row[tid + i * 256];
        mx = fmaxf(mx, vals[i]);
    }
#pragma unroll
    for (int off = 16; off; off >>= 1)
        mx = fmaxf(mx, __shfl_xor_sync(0xffffffffu, mx, off));
    __shared__ float sred[8];
    if ((tid & 31) == 0) sred[tid >> 5] = mx;
    __syncthreads();
    float bm = sred[0];
#pragma unroll
    for (int w = 1; w < 8; w++) bm = fmaxf(bm, sred[w]);
    __syncthreads();
    float sum = 0.f;
#pragma unroll
    for (int i = 0; i < 16; i++) { vals[i] = __expf(vals[i] - bm); sum += vals[i]; }
#pragma unroll
    for (int off = 16; off; off >>= 1)
        sum += __shfl_xor_sync(0xffffffffu, sum, off);
    if ((tid & 31) == 0) sred[tid >> 5] = sum;
    __syncthreads();
    float tot = 0.f;
#pragma unroll
    for (int w = 0; w < 8; w++) tot += sred[w];
    float inv = 1.0f / tot;
#pragma unroll
    for (int i = 0; i < 16; i++)
        out[(size_t)b * Sn + tid + i * 256] = vals[i] * inv;
}

// ---------------------------------------------------------------------------
extern "C" void kernel_launch(void* const* d_in, const int* in_sizes, int n_in,
                              void* d_out, int out_size) {
    const float* SE = (const float*)d_in[0];
    const float* DE = (const float*)d_in[1];
    const float* dh = (const float*)d_in[2];
    const float* v  = (const float*)d_in[3];
    const float* W  = (const float*)d_in[4];
    float* out = (float*)d_out;

    __half *wh; float *bias, *scores;
    cudaGetSymbolAddress((void**)&wh, g_Wh);
    cudaGetSymbolAddress((void**)&bias, g_bias);
    cudaGetSymbolAddress((void**)&scores, g_scores);

    cudaFuncSetAttribute(attn_main, cudaFuncAttributeMaxDynamicSharedMemorySize, SMEM_SZ);

    prep_kernel<<<2176, 256>>>(W, dh, wh, bias);
    attn_main<<<dim3(32, Bn), 512, SMEM_SZ>>>(SE, DE, wh, v, bias, scores);
    softmax_kernel<<<Bn, 256>>>(scores, out);
}